// round 8
// baseline (speedup 1.0000x reference)
#include <cuda_runtime.h>
#include <cuda_bf16.h>

#define N_EDGES   262144
#define EDGE_DIM  64
#define MAX_PATH  5
#define N_PAIRS   524288
#define OUT_ELEMS 16777216u   // 4096*4096

// Per-(edge, hop) dot table: 262144*5*4 B = 5.24 MB (L2-resident).
__device__ float g_dot[(size_t)N_EDGES * MAX_PATH];

// Kernel A': fused (a) zero the 67MB output, (b) Ddot[e][l] = dot(edge_attr[e], ev[l]).
// Layout: 4096 blocks x 256 threads. Per warp: 8 rows, 4 lanes per row.
// Each lane handles a 16-float quarter-row (4x float4), 5 hop-accumulators,
// then a 2-level shfl reduction within its 4-lane group (10 SHFL per warp total).
__global__ void __launch_bounds__(256) edge_dot_zero_kernel(
        const float* __restrict__ edge_attr,
        const float* __restrict__ edge_vector,
        float* __restrict__ out) {
    __shared__ float ev[MAX_PATH * EDGE_DIM];
    for (int i = threadIdx.x; i < MAX_PATH * EDGE_DIM; i += 256)
        ev[i] = edge_vector[i];
    __syncthreads();

    // --- grid-stride zero of the output (exactly 4 float4 per thread) ---
    {
        const size_t tid = (size_t)blockIdx.x * 256 + threadIdx.x;   // [0, 1048576)
        float4* o4 = reinterpret_cast<float4*>(out);
        const float4 z = make_float4(0.f, 0.f, 0.f, 0.f);
        #pragma unroll
        for (int i = 0; i < 4; i++)
            o4[tid + (size_t)i * 1048576] = z;                       // 4*1048576 = OUT/4
    }

    // --- edge-dot tile: 64 rows per block ---
    const int warp = threadIdx.x >> 5;
    const int lane = threadIdx.x & 31;
    const int j    = lane & 3;                        // quarter-row within group
    const int row  = blockIdx.x * 64 + warp * 8 + (lane >> 2);

    const float4* __restrict__ arow =
        reinterpret_cast<const float4*>(edge_attr + (size_t)row * EDGE_DIM + j * 16);

    float s0 = 0.f, s1 = 0.f, s2 = 0.f, s3 = 0.f, s4 = 0.f;
    #pragma unroll
    for (int k = 0; k < 4; k++) {
        const float4 a = arow[k];
        const int co = j * 16 + k * 4;                // ev column offset (16B aligned)
        #define ACC(L, S) { \
            const float4 e = *reinterpret_cast<const float4*>(ev + (L) * EDGE_DIM + co); \
            S += a.x * e.x + a.y * e.y + a.z * e.z + a.w * e.w; }
        ACC(0, s0) ACC(1, s1) ACC(2, s2) ACC(3, s3) ACC(4, s4)
        #undef ACC
    }

    // reduce within each 4-lane group (groups are 4-aligned, xor 1/2 stays inside)
    #pragma unroll
    for (int off = 1; off <= 2; off <<= 1) {
        s0 += __shfl_xor_sync(0xFFFFFFFFu, s0, off);
        s1 += __shfl_xor_sync(0xFFFFFFFFu, s1, off);
        s2 += __shfl_xor_sync(0xFFFFFFFFu, s2, off);
        s3 += __shfl_xor_sync(0xFFFFFFFFu, s3, off);
        s4 += __shfl_xor_sync(0xFFFFFFFFu, s4, off);
    }

    if (j == 0) {
        float* d = g_dot + (size_t)row * MAX_PATH;
        d[0] = s0; d[1] = s1; d[2] = s2; d[3] = s3; d[4] = s4;
    }
}

// Kernel B: per pair, masked mean of table gathers; scatter via pair_id (int32).
__global__ void __launch_bounds__(256) pair_kernel(
        const int* __restrict__ path_idx,
        const int* __restrict__ path_len,
        const int* __restrict__ pair_id,
        float* __restrict__ out) {
    const int p = blockIdx.x * blockDim.x + threadIdx.x;
    if (p >= N_PAIRS) return;

    const int len = path_len[p];
    const int* pi = path_idx + (size_t)p * MAX_PATH;

    // Load all 5 indices first (MLP), mask into range (branch-free, defensive),
    // gather unconditionally; predicate only the accumulation.
    int e0 = pi[0] & (N_EDGES - 1);
    int e1 = pi[1] & (N_EDGES - 1);
    int e2 = pi[2] & (N_EDGES - 1);
    int e3 = pi[3] & (N_EDGES - 1);
    int e4 = pi[4] & (N_EDGES - 1);

    float d0 = __ldg(&g_dot[(size_t)e0 * MAX_PATH + 0]);
    float d1 = __ldg(&g_dot[(size_t)e1 * MAX_PATH + 1]);
    float d2 = __ldg(&g_dot[(size_t)e2 * MAX_PATH + 2]);
    float d3 = __ldg(&g_dot[(size_t)e3 * MAX_PATH + 3]);
    float d4 = __ldg(&g_dot[(size_t)e4 * MAX_PATH + 4]);

    float s = 0.f;
    if (0 < len) s += d0;
    if (1 < len) s += d1;
    if (2 < len) s += d2;
    if (3 < len) s += d3;
    if (4 < len) s += d4;

    const float val = (len > 0) ? s / (float)len : 0.0f;

    unsigned int o = (unsigned int)pair_id[p] & (OUT_ELEMS - 1u);
    out[o] = val;
}

extern "C" void kernel_launch(void* const* d_in, const int* in_sizes, int n_in,
                              void* d_out, int out_size) {
    // metadata order: x, edge_attr, edge_vector, path_idx, path_len, pair_id
    const float* edge_attr   = (const float*)d_in[1];
    const float* edge_vector = (const float*)d_in[2];
    const int*   path_idx    = (const int*)d_in[3];
    const int*   path_len    = (const int*)d_in[4];
    const int*   pair_id     = (const int*)d_in[5];
    float* out = (float*)d_out;

    // Kernel A': 4096 blocks x 256 (64 edge rows per block + fused output zeroing).
    edge_dot_zero_kernel<<<4096, 256>>>(edge_attr, edge_vector, out);

    // Kernel B: thread per pair.
    pair_kernel<<<N_PAIRS / 256, 256>>>(path_idx, path_len, pair_id, out);
}

// round 9
// speedup vs baseline: 1.0044x; 1.0044x over previous
#include <cuda_runtime.h>
#include <cuda_bf16.h>

#define N_EDGES   262144
#define EDGE_DIM  64
#define MAX_PATH  5
#define N_PAIRS   524288
#define OUT_ELEMS 16777216u   // 4096*4096

// Per-(edge, hop) dot table: 262144*5*4 B = 5.24 MB (L2-resident).
__device__ float g_dot[(size_t)N_EDGES * MAX_PATH];

// Kernel A': fused (a) zero the 67MB output, (b) Ddot[e][l] = dot(edge_attr[e], ev[l]).
// Layout: 4096 blocks x 256 threads. Per warp: 8 rows, 4 lanes per row.
// Each lane handles a 16-float quarter-row (4x float4), 5 hop-accumulators,
// then a 2-level shfl reduction within its 4-lane group (10 SHFL per warp total).
__global__ void __launch_bounds__(256) edge_dot_zero_kernel(
        const float* __restrict__ edge_attr,
        const float* __restrict__ edge_vector,
        float* __restrict__ out) {
    __shared__ float ev[MAX_PATH * EDGE_DIM];
    for (int i = threadIdx.x; i < MAX_PATH * EDGE_DIM; i += 256)
        ev[i] = edge_vector[i];
    __syncthreads();

    // --- grid-stride zero of the output (exactly 4 float4 per thread) ---
    {
        const size_t tid = (size_t)blockIdx.x * 256 + threadIdx.x;   // [0, 1048576)
        float4* o4 = reinterpret_cast<float4*>(out);
        const float4 z = make_float4(0.f, 0.f, 0.f, 0.f);
        #pragma unroll
        for (int i = 0; i < 4; i++)
            o4[tid + (size_t)i * 1048576] = z;                       // 4*1048576 = OUT/4
    }

    // --- edge-dot tile: 64 rows per block ---
    const int warp = threadIdx.x >> 5;
    const int lane = threadIdx.x & 31;
    const int j    = lane & 3;                        // quarter-row within group
    const int row  = blockIdx.x * 64 + warp * 8 + (lane >> 2);

    const float4* __restrict__ arow =
        reinterpret_cast<const float4*>(edge_attr + (size_t)row * EDGE_DIM + j * 16);

    float s0 = 0.f, s1 = 0.f, s2 = 0.f, s3 = 0.f, s4 = 0.f;
    #pragma unroll
    for (int k = 0; k < 4; k++) {
        const float4 a = arow[k];
        const int co = j * 16 + k * 4;                // ev column offset (16B aligned)
        #define ACC(L, S) { \
            const float4 e = *reinterpret_cast<const float4*>(ev + (L) * EDGE_DIM + co); \
            S += a.x * e.x + a.y * e.y + a.z * e.z + a.w * e.w; }
        ACC(0, s0) ACC(1, s1) ACC(2, s2) ACC(3, s3) ACC(4, s4)
        #undef ACC
    }

    // reduce within each 4-lane group (groups are 4-aligned, xor 1/2 stays inside)
    #pragma unroll
    for (int off = 1; off <= 2; off <<= 1) {
        s0 += __shfl_xor_sync(0xFFFFFFFFu, s0, off);
        s1 += __shfl_xor_sync(0xFFFFFFFFu, s1, off);
        s2 += __shfl_xor_sync(0xFFFFFFFFu, s2, off);
        s3 += __shfl_xor_sync(0xFFFFFFFFu, s3, off);
        s4 += __shfl_xor_sync(0xFFFFFFFFu, s4, off);
    }

    if (j == 0) {
        float* d = g_dot + (size_t)row * MAX_PATH;
        d[0] = s0; d[1] = s1; d[2] = s2; d[3] = s3; d[4] = s4;
    }
}

// Kernel B: per pair, masked mean of table gathers; scatter via pair_id (int32).
__global__ void __launch_bounds__(256) pair_kernel(
        const int* __restrict__ path_idx,
        const int* __restrict__ path_len,
        const int* __restrict__ pair_id,
        float* __restrict__ out) {
    const int p = blockIdx.x * blockDim.x + threadIdx.x;
    if (p >= N_PAIRS) return;

    const int len = path_len[p];
    const int* pi = path_idx + (size_t)p * MAX_PATH;

    // Load all 5 indices first (MLP), mask into range (branch-free, defensive),
    // gather unconditionally; predicate only the accumulation.
    int e0 = pi[0] & (N_EDGES - 1);
    int e1 = pi[1] & (N_EDGES - 1);
    int e2 = pi[2] & (N_EDGES - 1);
    int e3 = pi[3] & (N_EDGES - 1);
    int e4 = pi[4] & (N_EDGES - 1);

    float d0 = __ldg(&g_dot[(size_t)e0 * MAX_PATH + 0]);
    float d1 = __ldg(&g_dot[(size_t)e1 * MAX_PATH + 1]);
    float d2 = __ldg(&g_dot[(size_t)e2 * MAX_PATH + 2]);
    float d3 = __ldg(&g_dot[(size_t)e3 * MAX_PATH + 3]);
    float d4 = __ldg(&g_dot[(size_t)e4 * MAX_PATH + 4]);

    float s = 0.f;
    if (0 < len) s += d0;
    if (1 < len) s += d1;
    if (2 < len) s += d2;
    if (3 < len) s += d3;
    if (4 < len) s += d4;

    const float val = (len > 0) ? s / (float)len : 0.0f;

    unsigned int o = (unsigned int)pair_id[p] & (OUT_ELEMS - 1u);
    out[o] = val;
}

extern "C" void kernel_launch(void* const* d_in, const int* in_sizes, int n_in,
                              void* d_out, int out_size) {
    // metadata order: x, edge_attr, edge_vector, path_idx, path_len, pair_id
    const float* edge_attr   = (const float*)d_in[1];
    const float* edge_vector = (const float*)d_in[2];
    const int*   path_idx    = (const int*)d_in[3];
    const int*   path_len    = (const int*)d_in[4];
    const int*   pair_id     = (const int*)d_in[5];
    float* out = (float*)d_out;

    // Kernel A': 4096 blocks x 256 (64 edge rows per block + fused output zeroing).
    edge_dot_zero_kernel<<<4096, 256>>>(edge_attr, edge_vector, out);

    // Kernel B: thread per pair.
    pair_kernel<<<N_PAIRS / 256, 256>>>(path_idx, path_len, pair_id, out);
}

// round 10
// speedup vs baseline: 1.0406x; 1.0361x over previous
#include <cuda_runtime.h>
#include <cuda_bf16.h>

#define N_EDGES   262144
#define EDGE_DIM  64
#define MAX_PATH  5
#define N_PAIRS   524288
#define OUT_ELEMS 16777216u   // 4096*4096

// Per-(edge, hop) dot table: 262144*5*4 B = 5.24 MB (L2-resident).
__device__ float g_dot[(size_t)N_EDGES * MAX_PATH];

// Kernel A': fused (a) zero the 67MB output, (b) Ddot[e][l] = dot(edge_attr[e], ev[l]).
// Layout: 4096 blocks x 256 threads. Per warp: 8 rows, 4 lanes per row.
// Each lane handles a 16-float quarter-row (4x float4), 5 hop-accumulators,
// then a 2-level shfl reduction within its 4-lane group (10 SHFL per warp total).
__global__ void __launch_bounds__(256) edge_dot_zero_kernel(
        const float* __restrict__ edge_attr,
        const float* __restrict__ edge_vector,
        float* __restrict__ out) {
    __shared__ float ev[MAX_PATH * EDGE_DIM];
    for (int i = threadIdx.x; i < MAX_PATH * EDGE_DIM; i += 256)
        ev[i] = edge_vector[i];
    __syncthreads();

    // --- grid-stride zero of the output (exactly 4 float4 per thread) ---
    {
        const size_t tid = (size_t)blockIdx.x * 256 + threadIdx.x;   // [0, 1048576)
        float4* o4 = reinterpret_cast<float4*>(out);
        const float4 z = make_float4(0.f, 0.f, 0.f, 0.f);
        #pragma unroll
        for (int i = 0; i < 4; i++)
            o4[tid + (size_t)i * 1048576] = z;                       // 4*1048576 = OUT/4
    }

    // --- edge-dot tile: 64 rows per block ---
    const int warp = threadIdx.x >> 5;
    const int lane = threadIdx.x & 31;
    const int j    = lane & 3;                        // quarter-row within group
    const int row  = blockIdx.x * 64 + warp * 8 + (lane >> 2);

    const float4* __restrict__ arow =
        reinterpret_cast<const float4*>(edge_attr + (size_t)row * EDGE_DIM + j * 16);

    float s0 = 0.f, s1 = 0.f, s2 = 0.f, s3 = 0.f, s4 = 0.f;
    #pragma unroll
    for (int k = 0; k < 4; k++) {
        const float4 a = arow[k];
        const int co = j * 16 + k * 4;                // ev column offset (16B aligned)
        #define ACC(L, S) { \
            const float4 e = *reinterpret_cast<const float4*>(ev + (L) * EDGE_DIM + co); \
            S += a.x * e.x + a.y * e.y + a.z * e.z + a.w * e.w; }
        ACC(0, s0) ACC(1, s1) ACC(2, s2) ACC(3, s3) ACC(4, s4)
        #undef ACC
    }

    // reduce within each 4-lane group (groups are 4-aligned, xor 1/2 stays inside)
    #pragma unroll
    for (int off = 1; off <= 2; off <<= 1) {
        s0 += __shfl_xor_sync(0xFFFFFFFFu, s0, off);
        s1 += __shfl_xor_sync(0xFFFFFFFFu, s1, off);
        s2 += __shfl_xor_sync(0xFFFFFFFFu, s2, off);
        s3 += __shfl_xor_sync(0xFFFFFFFFu, s3, off);
        s4 += __shfl_xor_sync(0xFFFFFFFFu, s4, off);
    }

    if (j == 0) {
        float* d = g_dot + (size_t)row * MAX_PATH;
        d[0] = s0; d[1] = s1; d[2] = s2; d[3] = s3; d[4] = s4;
    }
}

// Kernel B: per pair, masked mean of table gathers; scatter via pair_id (int32).
__global__ void __launch_bounds__(256) pair_kernel(
        const int* __restrict__ path_idx,
        const int* __restrict__ path_len,
        const int* __restrict__ pair_id,
        float* __restrict__ out) {
    const int p = blockIdx.x * blockDim.x + threadIdx.x;
    if (p >= N_PAIRS) return;

    const int len = path_len[p];
    const int* pi = path_idx + (size_t)p * MAX_PATH;

    // Load all 5 indices first (MLP), mask into range (branch-free, defensive),
    // gather unconditionally; predicate only the accumulation.
    int e0 = pi[0] & (N_EDGES - 1);
    int e1 = pi[1] & (N_EDGES - 1);
    int e2 = pi[2] & (N_EDGES - 1);
    int e3 = pi[3] & (N_EDGES - 1);
    int e4 = pi[4] & (N_EDGES - 1);

    float d0 = __ldg(&g_dot[(size_t)e0 * MAX_PATH + 0]);
    float d1 = __ldg(&g_dot[(size_t)e1 * MAX_PATH + 1]);
    float d2 = __ldg(&g_dot[(size_t)e2 * MAX_PATH + 2]);
    float d3 = __ldg(&g_dot[(size_t)e3 * MAX_PATH + 3]);
    float d4 = __ldg(&g_dot[(size_t)e4 * MAX_PATH + 4]);

    float s = 0.f;
    if (0 < len) s += d0;
    if (1 < len) s += d1;
    if (2 < len) s += d2;
    if (3 < len) s += d3;
    if (4 < len) s += d4;

    const float val = (len > 0) ? s / (float)len : 0.0f;

    unsigned int o = (unsigned int)pair_id[p] & (OUT_ELEMS - 1u);
    out[o] = val;
}

extern "C" void kernel_launch(void* const* d_in, const int* in_sizes, int n_in,
                              void* d_out, int out_size) {
    // metadata order: x, edge_attr, edge_vector, path_idx, path_len, pair_id
    const float* edge_attr   = (const float*)d_in[1];
    const float* edge_vector = (const float*)d_in[2];
    const int*   path_idx    = (const int*)d_in[3];
    const int*   path_len    = (const int*)d_in[4];
    const int*   pair_id     = (const int*)d_in[5];
    float* out = (float*)d_out;

    // Kernel A': 4096 blocks x 256 (64 edge rows per block + fused output zeroing).
    edge_dot_zero_kernel<<<4096, 256>>>(edge_attr, edge_vector, out);

    // Kernel B: thread per pair.
    pair_kernel<<<N_PAIRS / 256, 256>>>(path_idx, path_len, pair_id, out);
}